// round 8
// baseline (speedup 1.0000x reference)
#include <cuda_runtime.h>
#include <cuda_bf16.h>
#include <cstdint>

// Problem constants: B=2, L=2048, D=1024, H=16, d=64
#define L_SEQ   2048
#define D_MODEL 1024
#define NHEADS  16
#define DHEAD   64
#define CHUNK   64
#define NCHUNK  32
#define MROWS   4096            // B * L
#define TRIPLE  3072            // 3 * D

// fp32 scratch
__device__ float g_qkv[(size_t)MROWS * TRIPLE];            // [B*L, 3D]
__device__ float g_kv [(size_t)1024 * 4096];               // [B*H*NC, 64*64]

// bf16 split planes (row-major, K contiguous)
__device__ __nv_bfloat16 g_xh[(size_t)MROWS * D_MODEL];
__device__ __nv_bfloat16 g_xl[(size_t)MROWS * D_MODEL];
__device__ __nv_bfloat16 g_wh[(size_t)TRIPLE * D_MODEL];
__device__ __nv_bfloat16 g_wl[(size_t)TRIPLE * D_MODEL];
__device__ __nv_bfloat16 g_yh[(size_t)MROWS * D_MODEL];
__device__ __nv_bfloat16 g_yl[(size_t)MROWS * D_MODEL];
__device__ __nv_bfloat16 g_owh[(size_t)D_MODEL * D_MODEL];
__device__ __nv_bfloat16 g_owl[(size_t)D_MODEL * D_MODEL];

// ---------------------------------------------------------------------------
// helpers
// ---------------------------------------------------------------------------
__device__ __forceinline__ uint32_t smem_u32(const void* p) {
    uint32_t a;
    asm("{ .reg .u64 t; cvta.to.shared.u64 t, %1; cvt.u32.u64 %0, t; }"
        : "=r"(a) : "l"(p));
    return a;
}

#define CP_ASYNC16(dst_u32, src_ptr) \
    asm volatile("cp.async.cg.shared.global [%0], [%1], 16;" \
                 :: "r"(dst_u32), "l"(src_ptr))
#define CP_COMMIT()  asm volatile("cp.async.commit_group;" ::: "memory")
#define CP_WAIT0()   asm volatile("cp.async.wait_group 0;"  ::: "memory")
#define CP_WAIT1()   asm volatile("cp.async.wait_group 1;"  ::: "memory")

__device__ __forceinline__ void ldmx4(unsigned* r, uint32_t addr) {
    asm volatile("ldmatrix.sync.aligned.m8n8.x4.shared.b16 {%0,%1,%2,%3}, [%4];"
                 : "=r"(r[0]), "=r"(r[1]), "=r"(r[2]), "=r"(r[3]) : "r"(addr));
}

__device__ __forceinline__ void mma16816(float* d, const unsigned* a, const unsigned* b)
{
    asm volatile(
        "mma.sync.aligned.m16n8k16.row.col.f32.bf16.bf16.f32 "
        "{%0,%1,%2,%3}, {%4,%5,%6,%7}, {%8,%9}, {%0,%1,%2,%3};\n"
        : "+f"(d[0]), "+f"(d[1]), "+f"(d[2]), "+f"(d[3])
        : "r"(a[0]), "r"(a[1]), "r"(a[2]), "r"(a[3]), "r"(b[0]), "r"(b[1]));
}

// smem tile: 128 rows x 32B (16 bf16), XOR swizzle for conflict-free ldmatrix
__device__ __forceinline__ uint32_t swz(int row, int k16) {
    return (uint32_t)((row*32 + k16*16) ^ ((row & 4) << 2));
}

// ---------------------------------------------------------------------------
// fp32 -> (bf16 hi, bf16 lo) split conversion, float4-vectorized.
// ---------------------------------------------------------------------------
__device__ __forceinline__ void cvt_body(const float* __restrict__ in,
                                         __nv_bfloat16* __restrict__ hi,
                                         __nv_bfloat16* __restrict__ lo,
                                         int n4)
{
    int i = blockIdx.x * blockDim.x + threadIdx.x;
    if (i >= n4) return;
    float4 v = ((const float4*)in)[i];
    __nv_bfloat16 h0 = __float2bfloat16(v.x);
    __nv_bfloat16 h1 = __float2bfloat16(v.y);
    __nv_bfloat16 h2 = __float2bfloat16(v.z);
    __nv_bfloat16 h3 = __float2bfloat16(v.w);
    __nv_bfloat162 hh0; hh0.x = h0; hh0.y = h1;
    __nv_bfloat162 hh1; hh1.x = h2; hh1.y = h3;
    __nv_bfloat162 ll0, ll1;
    ll0.x = __float2bfloat16(v.x - __bfloat162float(h0));
    ll0.y = __float2bfloat16(v.y - __bfloat162float(h1));
    ll1.x = __float2bfloat16(v.z - __bfloat162float(h2));
    ll1.y = __float2bfloat16(v.w - __bfloat162float(h3));
    ((__nv_bfloat162*)hi)[i*2+0] = hh0;
    ((__nv_bfloat162*)hi)[i*2+1] = hh1;
    ((__nv_bfloat162*)lo)[i*2+0] = ll0;
    ((__nv_bfloat162*)lo)[i*2+1] = ll1;
}

__global__ void cvt_x (const float* __restrict__ in) { cvt_body(in, g_xh,  g_xl,  MROWS*D_MODEL/4); }
__global__ void cvt_w (const float* __restrict__ in) { cvt_body(in, g_wh,  g_wl,  TRIPLE*D_MODEL/4); }
__global__ void cvt_ow(const float* __restrict__ in) { cvt_body(in, g_owh, g_owl, D_MODEL*D_MODEL/4); }

// ---------------------------------------------------------------------------
// bf16-split tensor-core GEMM (NT): C[M,N] = A[M,K] @ B[N,K]^T + bias[N]
// 128x128 tile, BK=16, 3-stage cp.async pipeline (48KB static smem),
// ldmatrix x4 fragments, 2 CTAs/SM. K fixed at 1024.
// ---------------------------------------------------------------------------
#define GKK     1024
#define NITQ    (GKK/16)     // 64 k-tiles
#define PLANE_B 4096         // 128 rows * 32B
#define STAGE_B (4*PLANE_B)  // 16KB: Ah, Al, Bh, Bl

template<int N>
__device__ __forceinline__ void gemm_body(
    const __nv_bfloat16* __restrict__ Ahi, const __nv_bfloat16* __restrict__ Alo,
    const __nv_bfloat16* __restrict__ Bhi, const __nv_bfloat16* __restrict__ Blo,
    const float* __restrict__ bias, float* __restrict__ C)
{
    __shared__ __align__(16) char sbuf[3][STAGE_B];   // 48KB

    const int tid  = threadIdx.x;
    const int warp = tid >> 5;
    const int lane = tid & 31;
    const int wm   = warp & 1;          // 0..1 -> 64-row half (M)
    const int wn   = warp >> 1;         // 0..3 -> 32-col quarter (N)
    const int g    = lane >> 2;         // 0..7
    const int t    = lane & 3;          // 0..3
    const int m0   = blockIdx.y * 128;
    const int n0   = blockIdx.x * 128;

    const uint32_t ubase = smem_u32(sbuf);

    // ---- cp.async coordinates: each thread owns one 16B chunk per plane ----
    const int ldrow = tid >> 1;          // 0..127
    const int ldk16 = tid & 1;           // 0..1
    const uint32_t soff = swz(ldrow, ldk16);
    const size_t gA = (size_t)(m0 + ldrow) * GKK + ldk16*8;
    const size_t gB = (size_t)(n0 + ldrow) * GKK + ldk16*8;

    // ---- ldmatrix per-lane addresses ----
    const int lrow = lane & 7;
    const int sel  = lane >> 3;          // 0..3
    const int fr   = (sel & 1) * 8 + lrow;  // row within 16-row block
    const int fk   = sel >> 1;              // k16 half selector
    uint32_t aoff[4], boff[2];
    #pragma unroll
    for (int mt = 0; mt < 4; mt++) aoff[mt] = swz(wm*64 + mt*16 + fr, fk);
    #pragma unroll
    for (int np = 0; np < 2; np++) boff[np] = swz(wn*32 + np*16 + fr, fk);

    float acc[4][4][4];
    #pragma unroll
    for (int mt = 0; mt < 4; mt++)
        #pragma unroll
        for (int nt = 0; nt < 4; nt++)
            #pragma unroll
            for (int r = 0; r < 4; r++) acc[mt][nt][r] = 0.f;

    // ---- prologue: stages 0 and 1 ----
    #pragma unroll
    for (int pre = 0; pre < 2; pre++) {
        const uint32_t ub = ubase + pre*STAGE_B;
        const int k0 = pre * 16;
        CP_ASYNC16(ub + 0*PLANE_B + soff, &Ahi[gA + k0]);
        CP_ASYNC16(ub + 1*PLANE_B + soff, &Alo[gA + k0]);
        CP_ASYNC16(ub + 2*PLANE_B + soff, &Bhi[gB + k0]);
        CP_ASYNC16(ub + 3*PLANE_B + soff, &Blo[gB + k0]);
        CP_COMMIT();
    }

    int stage = 0;
    for (int it = 0; it < NITQ; ++it) {
        // tile `it` resident (allow tile it+1 in flight)
        if (it + 1 < NITQ) { CP_WAIT1(); } else { CP_WAIT0(); }
        __syncthreads();

        // issue tile it+2 into the stage freed two iterations ago
        if (it + 2 < NITQ) {
            const uint32_t ub = ubase + ((stage + 2) % 3) * STAGE_B;
            const int k0 = (it + 2) * 16;
            CP_ASYNC16(ub + 0*PLANE_B + soff, &Ahi[gA + k0]);
            CP_ASYNC16(ub + 1*PLANE_B + soff, &Alo[gA + k0]);
            CP_ASYNC16(ub + 2*PLANE_B + soff, &Bhi[gB + k0]);
            CP_ASYNC16(ub + 3*PLANE_B + soff, &Blo[gB + k0]);
            CP_COMMIT();
        } else {
            CP_COMMIT();   // keep group count in lockstep with waits
        }

        // ---- compute from current stage ----
        const uint32_t ub  = ubase + stage * STAGE_B;
        unsigned ah[4][4], al[4][4], bh[4][2], bl[4][2];
        #pragma unroll
        for (int mt = 0; mt < 4; mt++) {
            ldmx4(ah[mt], ub + 0*PLANE_B + aoff[mt]);
            ldmx4(al[mt], ub + 1*PLANE_B + aoff[mt]);
        }
        #pragma unroll
        for (int np = 0; np < 2; np++) {
            unsigned r4[4];
            ldmx4(r4, ub + 2*PLANE_B + boff[np]);
            bh[2*np][0] = r4[0]; bh[2*np][1]   = r4[2];
            bh[2*np+1][0] = r4[1]; bh[2*np+1][1] = r4[3];
            ldmx4(r4, ub + 3*PLANE_B + boff[np]);
            bl[2*np][0] = r4[0]; bl[2*np][1]   = r4[2];
            bl[2*np+1][0] = r4[1]; bl[2*np+1][1] = r4[3];
        }
        #pragma unroll
        for (int mt = 0; mt < 4; mt++)
            #pragma unroll
            for (int nt = 0; nt < 4; nt++) {
                mma16816(acc[mt][nt], ah[mt], bh[nt]);  // hi*hi
                mma16816(acc[mt][nt], ah[mt], bl[nt]);  // hi*lo
                mma16816(acc[mt][nt], al[mt], bh[nt]);  // lo*hi
            }

        stage = (stage + 1) % 3;
    }

    // ---- epilogue: C[r][c] = acc + bias[c] ----
    #pragma unroll
    for (int mt = 0; mt < 4; mt++) {
        int r = m0 + wm*64 + mt*16 + g;
        #pragma unroll
        for (int nt = 0; nt < 4; nt++) {
            int c = n0 + wn*32 + nt*8 + 2*t;
            float b0 = bias[c], b1 = bias[c+1];
            float2 o0 = make_float2(acc[mt][nt][0] + b0, acc[mt][nt][1] + b1);
            float2 o1 = make_float2(acc[mt][nt][2] + b0, acc[mt][nt][3] + b1);
            *(float2*)&C[(size_t)r * N + c]       = o0;
            *(float2*)&C[(size_t)(r+8) * N + c]   = o1;
        }
    }
}

__global__ __launch_bounds__(256, 2) void gemm_qkv_bf16(const float* __restrict__ bias)
{
    gemm_body<TRIPLE>(g_xh, g_xl, g_wh, g_wl, bias, g_qkv);
}

__global__ __launch_bounds__(256, 2) void gemm_out_bf16(const float* __restrict__ bias,
                                                        float* __restrict__ C)
{
    gemm_body<D_MODEL>(g_yh, g_yl, g_owh, g_owl, bias, C);
}

// ---------------------------------------------------------------------------
// Per-(b,h,chunk): KV = K_c^T V_c  (64x64), K pre-scaled by 1/sqrt(d)=0.125
// ---------------------------------------------------------------------------
__global__ __launch_bounds__(256) void chunk_kv_kernel()
{
    __shared__ float Ks[64][64];
    __shared__ float Vs[64][64];
    const int blk = blockIdx.x;            // bh*32 + c
    const int c   = blk & 31;
    const int bh  = blk >> 5;
    const int h   = bh & 15;
    const int b   = bh >> 4;
    const int tid = threadIdx.x;
    const int t0g = c * CHUNK;

    for (int idx = tid; idx < 64*16; idx += 256) {
        int r = idx >> 4, c4 = idx & 15;
        size_t base = ((size_t)(b*L_SEQ + t0g + r)) * TRIPLE + h*DHEAD + c4*4;
        float4 k4 = *(const float4*)(g_qkv + base + 1024);
        float4 v4 = *(const float4*)(g_qkv + base + 2048);
        k4.x *= 0.125f; k4.y *= 0.125f; k4.z *= 0.125f; k4.w *= 0.125f;
        *(float4*)&Ks[r][c4*4] = k4;
        *(float4*)&Vs[r][c4*4] = v4;
    }
    __syncthreads();

    const int i0 = (tid >> 4) * 4;
    const int j0 = (tid & 15) * 4;
    float acc[4][4] = {};
    #pragma unroll 8
    for (int t = 0; t < 64; t++) {
        float k4[4], v4[4];
        *(float4*)k4 = *(const float4*)&Ks[t][i0];
        *(float4*)v4 = *(const float4*)&Vs[t][j0];
        #pragma unroll
        for (int ii = 0; ii < 4; ii++)
            #pragma unroll
            for (int jj = 0; jj < 4; jj++)
                acc[ii][jj] = fmaf(k4[ii], v4[jj], acc[ii][jj]);
    }
    float* outp = g_kv + (size_t)blk * 4096;
    #pragma unroll
    for (int ii = 0; ii < 4; ii++)
        *(float4*)(outp + (i0+ii)*64 + j0) =
            make_float4(acc[ii][0], acc[ii][1], acc[ii][2], acc[ii][3]);
}

// ---------------------------------------------------------------------------
// In-place exclusive prefix over chunks: S_c = sum_{c'<c} KV_{c'}
// ---------------------------------------------------------------------------
__global__ __launch_bounds__(256) void prefix_kernel()
{
    const int bh = blockIdx.x;
    const size_t base0 = (size_t)bh * NCHUNK * 4096;
    for (int e = threadIdx.x; e < 4096; e += 256) {
        float run = 0.f;
        size_t base = base0 + e;
        #pragma unroll
        for (int c = 0; c < NCHUNK; c++) {
            float t = g_kv[base + (size_t)c * 4096];
            g_kv[base + (size_t)c * 4096] = run;
            run += t;
        }
    }
}

// ---------------------------------------------------------------------------
// Per-(b,h,chunk) output: y = Q @ S + (Q K^T (.) tril) @ V
// Writes y directly as bf16 hi/lo split planes.
// ---------------------------------------------------------------------------
__global__ __launch_bounds__(256) void chunk_out_kernel()
{
    __shared__ float Qs[64][64];   // Qs[i][t]  (transposed)
    __shared__ float Bs[64][64];   // S natural -> K^T [i][s] -> V natural
    __shared__ float Ps[64][64];   // Ps[s][t]

    const int blk = blockIdx.x;
    const int c   = blk & 31;
    const int bh  = blk >> 5;
    const int h   = bh & 15;
    const int b   = bh >> 4;
    const int tid = threadIdx.x;
    const int t0  = (tid >> 4) * 4;
    const int j0  = (tid & 15) * 4;
    const int ct0 = c * CHUNK;

    for (int idx = tid; idx < 64*16; idx += 256) {
        int r = idx >> 4, c4 = idx & 15;
        size_t base = ((size_t)(b*L_SEQ + ct0 + r)) * TRIPLE + h*DHEAD + c4*4;
        float4 q4 = *(const float4*)(g_qkv + base);
        Qs[c4*4+0][r] = q4.x; Qs[c4*4+1][r] = q4.y;
        Qs[c4*4+2][r] = q4.z; Qs[c4*4+3][r] = q4.w;
        *(float4*)&Bs[r][c4*4] =
            *(const float4*)(g_kv + (size_t)blk * 4096 + r*64 + c4*4);
    }
    __syncthreads();

    float acc[4][4] = {};
    #pragma unroll 8
    for (int i = 0; i < 64; i++) {
        float q4[4], s4[4];
        *(float4*)q4 = *(const float4*)&Qs[i][t0];
        *(float4*)s4 = *(const float4*)&Bs[i][j0];
        #pragma unroll
        for (int tt = 0; tt < 4; tt++)
            #pragma unroll
            for (int jj = 0; jj < 4; jj++)
                acc[tt][jj] = fmaf(q4[tt], s4[jj], acc[tt][jj]);
    }
    __syncthreads();

    for (int idx = tid; idx < 64*16; idx += 256) {
        int r = idx >> 4, c4 = idx & 15;
        size_t base = ((size_t)(b*L_SEQ + ct0 + r)) * TRIPLE + 1024 + h*DHEAD + c4*4;
        float4 k4 = *(const float4*)(g_qkv + base);
        Bs[c4*4+0][r] = k4.x * 0.125f; Bs[c4*4+1][r] = k4.y * 0.125f;
        Bs[c4*4+2][r] = k4.z * 0.125f; Bs[c4*4+3][r] = k4.w * 0.125f;
    }
    __syncthreads();

    {
        float pacc[4][4] = {};
        #pragma unroll 8
        for (int i = 0; i < 64; i++) {
            float k4[4], q4[4];
            *(float4*)k4 = *(const float4*)&Bs[i][t0];   // K^T: [i][s]
            *(float4*)q4 = *(const float4*)&Qs[i][j0];   // Q^T: [i][t]
            #pragma unroll
            for (int ss = 0; ss < 4; ss++)
                #pragma unroll
                for (int tt = 0; tt < 4; tt++)
                    pacc[ss][tt] = fmaf(k4[ss], q4[tt], pacc[ss][tt]);
        }
        #pragma unroll
        for (int ss = 0; ss < 4; ss++) {
            int s = t0 + ss;
            float4 o;
            o.x = (j0+0 >= s) ? pacc[ss][0] : 0.f;
            o.y = (j0+1 >= s) ? pacc[ss][1] : 0.f;
            o.z = (j0+2 >= s) ? pacc[ss][2] : 0.f;
            o.w = (j0+3 >= s) ? pacc[ss][3] : 0.f;
            *(float4*)&Ps[s][j0] = o;
        }
    }
    __syncthreads();

    for (int idx = tid; idx < 64*16; idx += 256) {
        int r = idx >> 4, c4 = idx & 15;
        size_t base = ((size_t)(b*L_SEQ + ct0 + r)) * TRIPLE + 2048 + h*DHEAD + c4*4;
        *(float4*)&Bs[r][c4*4] = *(const float4*)(g_qkv + base);
    }
    __syncthreads();

    #pragma unroll 8
    for (int s = 0; s < 64; s++) {
        float p4[4], v4[4];
        *(float4*)p4 = *(const float4*)&Ps[s][t0];
        *(float4*)v4 = *(const float4*)&Bs[s][j0];
        #pragma unroll
        for (int tt = 0; tt < 4; tt++)
            #pragma unroll
            for (int jj = 0; jj < 4; jj++)
                acc[tt][jj] = fmaf(p4[tt], v4[jj], acc[tt][jj]);
    }

    // Store y as bf16 hi/lo split (for the output GEMM)
    #pragma unroll
    for (int tt = 0; tt < 4; tt++) {
        size_t off = ((size_t)(b*L_SEQ + ct0 + t0 + tt)) * D_MODEL + h*DHEAD + j0;
        __nv_bfloat162 h01, h23, l01, l23;
        h01.x = __float2bfloat16(acc[tt][0]);
        h01.y = __float2bfloat16(acc[tt][1]);
        h23.x = __float2bfloat16(acc[tt][2]);
        h23.y = __float2bfloat16(acc[tt][3]);
        l01.x = __float2bfloat16(acc[tt][0] - __bfloat162float(h01.x));
        l01.y = __float2bfloat16(acc[tt][1] - __bfloat162float(h01.y));
        l23.x = __float2bfloat16(acc[tt][2] - __bfloat162float(h23.x));
        l23.y = __float2bfloat16(acc[tt][3] - __bfloat162float(h23.y));
        *(__nv_bfloat162*)&g_yh[off]     = h01;
        *(__nv_bfloat162*)&g_yh[off + 2] = h23;
        *(__nv_bfloat162*)&g_yl[off]     = l01;
        *(__nv_bfloat162*)&g_yl[off + 2] = l23;
    }
}

// ---------------------------------------------------------------------------
extern "C" void kernel_launch(void* const* d_in, const int* in_sizes, int n_in,
                              void* d_out, int out_size)
{
    const float* x      = (const float*)d_in[0];
    const float* Wqkv_w = (const float*)d_in[1];
    const float* Wqkv_b = (const float*)d_in[2];
    const float* out_w  = (const float*)d_in[3];
    const float* out_b  = (const float*)d_in[4];
    float* out = (float*)d_out;

    // 0) split-convert inputs/weights to bf16 hi/lo
    cvt_x <<<MROWS*D_MODEL/4/256,   256>>>(x);
    cvt_w <<<TRIPLE*D_MODEL/4/256,  256>>>(Wqkv_w);
    cvt_ow<<<D_MODEL*D_MODEL/4/256, 256>>>(out_w);

    // 1) QKV projection (tensor cores, 3-stage pipeline)
    gemm_qkv_bf16<<<dim3(TRIPLE/128, MROWS/128), 256>>>(Wqkv_b);

    // 2) Per-chunk KV = K^T V
    chunk_kv_kernel<<<1024, 256>>>();

    // 3) Exclusive prefix over chunks -> inter-chunk states S
    prefix_kernel<<<32, 256>>>();

    // 4) Per-chunk output: y = Q S + (Q K^T . tril) V  (writes bf16 split)
    chunk_out_kernel<<<1024, 256>>>();

    // 5) Output projection (tensor cores, 3-stage pipeline)
    gemm_out_bf16<<<dim3(D_MODEL/128, MROWS/128), 256>>>(out_b, out);
}